// round 2
// baseline (speedup 1.0000x reference)
#include <cuda_runtime.h>
#include <math.h>

typedef unsigned long long ull;

// Problem constants
#define Bz   64
#define Tz   1024
#define Dz   128
#define Hz   512
#define Gz   2048          // 4*H
#define BT   65536         // B*T
#define NCHUNK 256         // bn partial chunks

// ---------------- scratch (device globals; no cudaMalloc allowed) ----------
__device__ float    g_xg[(size_t)Tz * Bz * Gz];     // [T][B][4H]
__device__ float    g_h1[(size_t)BT * Hz];          // [B][T][H]
__device__ float    g_h2[(size_t)BT * Hz];          // [B][T][H]
__device__ float    g_hping[2][Bz * Hz];            // recurrent h double buffer
__device__ unsigned g_bar;                          // grid barrier counter
__device__ float    g_ps [NCHUNK * Hz];             // BN partial sums
__device__ float    g_ps2[NCHUNK * Hz];
__device__ float    g_bnA[Hz];                      // folded BN scale
__device__ float    g_bnB[Hz];                      // folded BN bias

// ---------------- f32x2 packed helpers ------------------------------------
__device__ __forceinline__ ull pack2(float x, float y) {
    ull r;
    asm("mov.b64 %0, {%1, %2};" : "=l"(r) : "f"(x), "f"(y));
    return r;
}
__device__ __forceinline__ float unpack_sum(ull v) {
    float lo, hi;
    asm("mov.b64 {%0, %1}, %2;" : "=f"(lo), "=f"(hi) : "l"(v));
    return lo + hi;
}
#define FMA2(acc, a, b) asm("fma.rn.f32x2 %0, %1, %2, %0;" : "+l"(acc) : "l"(a), "l"(b))

// ---------------------------------------------------------------------------
// SGEMM (f32x2, k-paired): out[t][b][:] = A[m][:K] @ W[K][2048] + bias
// BM=BN=128, BK=8 (4 k-pairs), 256 threads, per-thread 8x8, acc packed over k.
// ---------------------------------------------------------------------------
__global__ __launch_bounds__(256) void sgemm_xg(
    const float* __restrict__ A, const float* __restrict__ W,
    const float* __restrict__ bias, float* __restrict__ out, int K)
{
    __shared__ ull As2[4 * 130];   // [k2][m], pad to 130 (16B-aligned rows)
    __shared__ ull Bs2[4 * 160];   // [k2][slot(n)]: n-group g at slot g*10 (bank-spread)

    const int tid  = threadIdx.x;
    const int cCol = blockIdx.x;   // 0..15
    const int cRow = blockIdx.y;   // 0..511

    const float* Ap = A + (size_t)cRow * 128 * K;
    const float* Wp = W + cCol * 128;

    // staging roles
    const int mA  = tid >> 1;                  // 0..127
    const int caA = tid & 1;                   // k-quad within BK
    const int kk2 = tid >> 5;                  // 0..7 (B uses tid<128 -> 0..3)
    const int nb  = (tid & 31) * 4;            // 0..124
    // compute roles
    const int threadRow = tid >> 4;            // 0..15
    const int threadCol = tid & 15;            // 0..15

    ull acc[8][8];
#pragma unroll
    for (int i = 0; i < 8; i++)
#pragma unroll
        for (int j = 0; j < 8; j++) acc[i][j] = 0ull;

    for (int k0 = 0; k0 < K; k0 += 8) {
        // stage A: float4 = k pairs (2*caA, 2*caA+1) for row mA
        float4 ta = *reinterpret_cast<const float4*>(&Ap[(size_t)mA * K + k0 + caA * 4]);
        As2[(2 * caA + 0) * 130 + mA] = pack2(ta.x, ta.y);
        As2[(2 * caA + 1) * 130 + mA] = pack2(ta.z, ta.w);
        // stage B: 128 threads load 2 consecutive k-rows, write interleaved pairs
        if (tid < 128) {
            float4 r0 = *reinterpret_cast<const float4*>(&Wp[(size_t)(k0 + 2 * kk2 + 0) * Gz + nb]);
            float4 r1 = *reinterpret_cast<const float4*>(&Wp[(size_t)(k0 + 2 * kk2 + 1) * Gz + nb]);
            int slot = (nb >> 3) * 10 + (nb & 7);
            ull* bp = &Bs2[kk2 * 160 + slot];
            bp[0] = pack2(r0.x, r1.x);
            bp[1] = pack2(r0.y, r1.y);
            bp[2] = pack2(r0.z, r1.z);
            bp[3] = pack2(r0.w, r1.w);
        }
        __syncthreads();

#pragma unroll
        for (int d2 = 0; d2 < 4; d2++) {
            ull hr[8], wr[8];
            const ulonglong2* ap = reinterpret_cast<const ulonglong2*>(&As2[d2 * 130 + threadRow * 8]);
            const ulonglong2* bp = reinterpret_cast<const ulonglong2*>(&Bs2[d2 * 160 + threadCol * 10]);
#pragma unroll
            for (int q = 0; q < 4; q++) { ulonglong2 v = ap[q]; hr[2 * q] = v.x; hr[2 * q + 1] = v.y; }
#pragma unroll
            for (int q = 0; q < 4; q++) { ulonglong2 v = bp[q]; wr[2 * q] = v.x; wr[2 * q + 1] = v.y; }
#pragma unroll
            for (int i = 0; i < 8; i++)
#pragma unroll
                for (int j = 0; j < 8; j++) FMA2(acc[i][j], hr[i], wr[j]);
        }
        __syncthreads();
    }

    const int col0 = cCol * 128 + threadCol * 8;
#pragma unroll
    for (int i = 0; i < 8; i++) {
        int m  = cRow * 128 + threadRow * 8 + i;
        int bb = m >> 10;          // batch
        int tt = m & 1023;         // time
        float* orow = &out[(size_t)((tt << 6) + bb) << 11];
#pragma unroll
        for (int j = 0; j < 8; j += 4) {
            float4 bv = *reinterpret_cast<const float4*>(&bias[col0 + j]);
            float4 r;
            r.x = unpack_sum(acc[i][j + 0]) + bv.x;
            r.y = unpack_sum(acc[i][j + 1]) + bv.y;
            r.z = unpack_sum(acc[i][j + 2]) + bv.z;
            r.w = unpack_sum(acc[i][j + 3]) + bv.w;
            *reinterpret_cast<float4*>(&orow[col0 + j]) = r;
        }
    }
}

// ---------------------------------------------------------------------------
// reset: zero h ping buffer 0 + barrier counter
// ---------------------------------------------------------------------------
__global__ void reset_state()
{
    int i = blockIdx.x * 512 + threadIdx.x;
    g_hping[0][i] = 0.f;
    if (i == 0) g_bar = 0u;
}

// ---------------------------------------------------------------------------
// Persistent LSTM recurrence (f32x2 k-paired).
// 128 CTAs x 256 thr, 1/SM. CTA owns 4 units = 16 gate cols.
// smem (bytes): [0, 32768)           sW2: ull[256][16]   (k2 x col) pairs
//               [32768, 196608)      sH2: ull[256][80]   (k2 x b-slot) pairs,
//                                    b-group g at slot g*10 (bank-spread, conflict-free)
//               sR aliases sH2 base: float[16][1024] (split x (c*64+b)) — guarded by syncs
// 16 k-splits of 32 k (16 k2). Thread tile 8b x 8c, acc packed (even-k, odd-k).
// ---------------------------------------------------------------------------
#define SH2_ROW 80
#define REC_SMEM ((4096 + 256 * SH2_ROW) * 8)   // 196608 B

__device__ __forceinline__ float sigmoidf_(float x) { return 1.f / (1.f + expf(-x)); }

__global__ __launch_bounds__(256) void lstm_rec(
    const float* __restrict__ Wh,    // [512][2048]
    const float* __restrict__ xgp,   // [T][B][2048]
    float* __restrict__ hout)        // [B][T][512]
{
    extern __shared__ ull smu[];
    ull*   sW2 = smu;                 // 4096 ull
    ull*   sH2 = smu + 4096;          // 256*80 ull
    float* sR  = reinterpret_cast<float*>(smu + 4096);  // alias (64KB of sH2)

    const int tid = threadIdx.x;
    const int u0  = blockIdx.x * 4;

    // build sW2: pairs over k; col c = gate*4 + unit
    for (int i = tid; i < 256 * 16; i += 256) {
        int k2 = i >> 4, c = i & 15;
        int gate = c >> 2, un = c & 3;
        float lo = Wh[(size_t)(2 * k2 + 0) * Gz + gate * Hz + u0 + un];
        float hi = Wh[(size_t)(2 * k2 + 1) * Gz + gate * Hz + u0 + un];
        sW2[i] = pack2(lo, hi);
    }

    // dot roles: 16 k-splits x (8 b-groups x 2 c-groups)
    const int ks = tid >> 4;               // 0..15
    const int r  = tid & 15;
    const int b0 = (r >> 1) * 8;           // 0,8,..,56
    const int c0 = (r & 1) * 8;            // 0 or 8
    const int bslot = (b0 >> 3) * 10;      // b-group slot base
    // stage roles
    const int sb = tid >> 2;               // batch 0..63
    const int sq = tid & 3;
    const int scol = (sb >> 3) * 10 + (sb & 7);
    // finalize roles
    const int fb = tid & 63;
    const int fu = tid >> 6;

    float creg = 0.f;
    __syncthreads();

    for (int t = 0; t < Tz; t++) {
        // ---- stage h_prev [b][k] -> sH2 [k2][b-slot] as k-pairs ----
        const float* hp = &g_hping[t & 1][0];
#pragma unroll 4
        for (int i2 = 0; i2 < 32; i2++) {
            int k4 = i2 * 4 + sq;                   // float4 index
            float4 v = __ldcg(reinterpret_cast<const float4*>(&hp[sb * 512 + (k4 << 2)]));
            int k2a = k4 << 1;
            sH2[(k2a + 0) * SH2_ROW + scol] = pack2(v.x, v.y);
            sH2[(k2a + 1) * SH2_ROW + scol] = pack2(v.z, v.w);
        }
        __syncthreads();

        // ---- dot: acc[8][8] packed over k, this split's 16 k2 rows ----
        ull acc[8][8];
#pragma unroll
        for (int i = 0; i < 8; i++)
#pragma unroll
            for (int j = 0; j < 8; j++) acc[i][j] = 0ull;

        const int k2base = ks * 16;
#pragma unroll 2
        for (int kk = 0; kk < 16; kk++) {
            int k2 = k2base + kk;
            ull hr[8], wr[8];
            const ulonglong2* hp2 = reinterpret_cast<const ulonglong2*>(&sH2[k2 * SH2_ROW + bslot]);
#pragma unroll
            for (int q = 0; q < 4; q++) { ulonglong2 v = hp2[q]; hr[2 * q] = v.x; hr[2 * q + 1] = v.y; }
            const ulonglong2* wp2 = reinterpret_cast<const ulonglong2*>(&sW2[(k2 << 4) + c0]);
#pragma unroll
            for (int q = 0; q < 4; q++) { ulonglong2 v = wp2[q]; wr[2 * q] = v.x; wr[2 * q + 1] = v.y; }
#pragma unroll
            for (int i = 0; i < 8; i++)
#pragma unroll
                for (int j = 0; j < 8; j++) FMA2(acc[i][j], hr[i], wr[j]);
        }
        __syncthreads();   // all sH2 reads done before sR (aliased) writes

        // ---- write split partials (collapse even/odd halves) ----
#pragma unroll
        for (int i = 0; i < 8; i++)
#pragma unroll
            for (int j = 0; j < 8; j++)
                sR[(ks << 10) + ((c0 + j) << 6) + (b0 + i)] = unpack_sum(acc[i][j]);
        __syncthreads();

        // ---- finalize: reduce 16 splits, add xg, gate math, write h ----
        float gv[4];
#pragma unroll
        for (int g = 0; g < 4; g++) {
            int c = (g << 2) + fu;
            float s = 0.f;
#pragma unroll
            for (int kq = 0; kq < 16; kq++) s += sR[(kq << 10) + (c << 6) + fb];
            gv[g] = s + xgp[(size_t)((t << 6) + fb) * Gz + (g << 9) + u0 + fu];
        }
        float ig = sigmoidf_(gv[0]);
        float fg = sigmoidf_(gv[1]);
        float gg = tanhf(gv[2]);
        float og = sigmoidf_(gv[3]);
        creg = fg * creg + ig * gg;
        float hv = og * tanhf(creg);

        g_hping[(t & 1) ^ 1][fb * 512 + u0 + fu] = hv;
        hout[(size_t)((fb << 10) + t) * Hz + u0 + fu] = hv;

        // ---- grid barrier ----
        __threadfence();
        __syncthreads();
        if (tid == 0) {
            atomicAdd(&g_bar, 1u);
            unsigned tgt = (unsigned)(t + 1) * gridDim.x;
            volatile unsigned* vb = &g_bar;
            while (*vb < tgt) {}
        }
        __syncthreads();
    }
}

// ---------------------------------------------------------------------------
// BatchNorm (deterministic two-stage) + apply + head
// ---------------------------------------------------------------------------
__global__ void bn_partial(const float* __restrict__ h)
{
    int f = blockIdx.x * 128 + threadIdx.x;    // grid.x = 4
    int chunk = blockIdx.y;                    // grid.y = NCHUNK (256 rows each)
    const float* p = h + (size_t)chunk * (BT / NCHUNK) * Hz + f;
    float s = 0.f, s2 = 0.f;
    for (int r = 0; r < BT / NCHUNK; r++) {
        float v = p[(size_t)r * Hz];
        s += v; s2 += v * v;
    }
    g_ps [chunk * Hz + f] = s;
    g_ps2[chunk * Hz + f] = s2;
}

__global__ void bn_finalize(const float* __restrict__ scale, const float* __restrict__ bias)
{
    int f = blockIdx.x * 128 + threadIdx.x;
    float s = 0.f, s2 = 0.f;
    for (int c = 0; c < NCHUNK; c++) { s += g_ps[c * Hz + f]; s2 += g_ps2[c * Hz + f]; }
    float mean = s * (1.f / 65536.f);
    float var  = s2 * (1.f / 65536.f) - mean * mean;
    float rstd = rsqrtf(var + 1e-5f);
    float a = rstd * scale[f];
    g_bnA[f] = a;
    g_bnB[f] = bias[f] - mean * a;
}

__global__ void bn_apply(float* __restrict__ h)
{
    int idx = blockIdx.x * 256 + threadIdx.x;
    float4 v = reinterpret_cast<float4*>(h)[idx];
    int f = (idx & 127) * 4;
    float4 a = *reinterpret_cast<const float4*>(&g_bnA[f]);
    float4 b = *reinterpret_cast<const float4*>(&g_bnB[f]);
    v.x = v.x * a.x + b.x;
    v.y = v.y * a.y + b.y;
    v.z = v.z * a.z + b.z;
    v.w = v.w * a.w + b.w;
    reinterpret_cast<float4*>(h)[idx] = v;
}

__global__ void head_kernel(const float* __restrict__ h2,
                            const float* __restrict__ Wd1, const float* __restrict__ bd1,
                            const float* __restrict__ Wd2, const float* __restrict__ bd2,
                            float* __restrict__ out)
{
    __shared__ float sh[512];
    __shared__ float sy[16];
    int b = blockIdx.x;
    int tid = threadIdx.x;
    float v = h2[((size_t)b * 1024 + 1023) * Hz + tid];
    sh[tid] = v * g_bnA[tid] + g_bnB[tid];
    __syncthreads();

    int w = tid >> 5, lane = tid & 31;
    float s = 0.f;
    for (int f = lane; f < 512; f += 32) s += sh[f] * Wd1[f * 16 + w];
#pragma unroll
    for (int off = 16; off; off >>= 1) s += __shfl_down_sync(0xffffffffu, s, off);
    if (lane == 0) sy[w] = fmaxf(s + bd1[w], 0.f);
    __syncthreads();
    if (tid == 0) {
        float o = bd2[0];
#pragma unroll
        for (int j = 0; j < 16; j++) o += sy[j] * Wd2[j];
        out[b] = o;
    }
}

// ---------------------------------------------------------------------------
extern "C" void kernel_launch(void* const* d_in, const int* in_sizes, int n_in,
                              void* d_out, int out_size)
{
    const float* x    = (const float*)d_in[0];
    const float* Wx1  = (const float*)d_in[1];
    const float* Wh1  = (const float*)d_in[2];
    const float* b1   = (const float*)d_in[3];
    const float* s1   = (const float*)d_in[4];
    const float* bi1  = (const float*)d_in[5];
    const float* Wx2  = (const float*)d_in[6];
    const float* Wh2  = (const float*)d_in[7];
    const float* b2   = (const float*)d_in[8];
    const float* s2   = (const float*)d_in[9];
    const float* bi2  = (const float*)d_in[10];
    const float* Wd1  = (const float*)d_in[11];
    const float* bd1  = (const float*)d_in[12];
    const float* Wd2  = (const float*)d_in[13];
    const float* bd2  = (const float*)d_in[14];
    float* out = (float*)d_out;

    float *xg, *h1, *h2;
    cudaGetSymbolAddress((void**)&xg, g_xg);
    cudaGetSymbolAddress((void**)&h1, g_h1);
    cudaGetSymbolAddress((void**)&h2, g_h2);

    cudaFuncSetAttribute(lstm_rec, cudaFuncAttributeMaxDynamicSharedMemorySize, REC_SMEM);

    // layer 1
    sgemm_xg<<<dim3(16, 512), 256>>>(x, Wx1, b1, xg, Dz);
    reset_state<<<64, 512>>>();
    lstm_rec<<<128, 256, REC_SMEM>>>(Wh1, xg, h1);
    bn_partial<<<dim3(4, NCHUNK), 128>>>(h1);
    bn_finalize<<<4, 128>>>(s1, bi1);
    bn_apply<<<32768, 256>>>(h1);

    // layer 2
    sgemm_xg<<<dim3(16, 512), 256>>>(h1, Wx2, b2, xg, Hz);
    reset_state<<<64, 512>>>();
    lstm_rec<<<128, 256, REC_SMEM>>>(Wh2, xg, h2);
    bn_partial<<<dim3(4, NCHUNK), 128>>>(h2);
    bn_finalize<<<4, 128>>>(s2, bi2);

    // head (applies bn2 to last timestep only)
    head_kernel<<<64, 512>>>(h2, Wd1, bd1, Wd2, bd2, out);
}

// round 3
// speedup vs baseline: 1.1462x; 1.1462x over previous
#include <cuda_runtime.h>
#include <math.h>

// Problem constants
#define Bz   64
#define Tz   1024
#define Dz   128
#define Hz   512
#define Gz   2048          // 4*H
#define BT   65536         // B*T
#define NCHUNK 256         // bn partial chunks

// ---------------- scratch (device globals; no cudaMalloc allowed) ----------
__device__ float    g_xg[(size_t)Tz * Bz * Gz];     // [T][B][4H]
__device__ float    g_h1[(size_t)BT * Hz];          // [B][T][H]
__device__ float    g_h2[(size_t)BT * Hz];          // [B][T][H]
__device__ float    g_hping[2][Bz * Hz];            // recurrent h double buffer
__device__ unsigned g_bar;                          // grid barrier counter
__device__ float    g_ps [NCHUNK * Hz];             // BN partial sums
__device__ float    g_ps2[NCHUNK * Hz];
__device__ float    g_bnA[Hz];                      // folded BN scale
__device__ float    g_bnB[Hz];                      // folded BN bias

// ---------------------------------------------------------------------------
// Tensor-core SGEMM (tf32 x3 precision split):
//   out[t][b][:] = A[m][:K] @ W[K][2048] + bias,  scattered to [T][B][G]
// Block 128x128, BK=32, 8 warps (warp tile 64x32), cp.async 3-stage pipeline.
// smem strides: A rows 36 words, B rows 136 words (conflict-free frag loads).
// ---------------------------------------------------------------------------
#define A_STRIDE 36
#define B_STRIDE 136
#define STAGE_FLOATS (128 * A_STRIDE + 32 * B_STRIDE)   // 4608 + 4352 = 8960
#define GEMM_SMEM (3 * STAGE_FLOATS * 4)                // 107520 B

__device__ __forceinline__ void mma_tf32(float* c, const unsigned* a, const unsigned* b)
{
    asm volatile(
        "mma.sync.aligned.m16n8k8.row.col.f32.tf32.tf32.f32 "
        "{%0,%1,%2,%3}, {%4,%5,%6,%7}, {%8,%9}, {%0,%1,%2,%3};"
        : "+f"(c[0]), "+f"(c[1]), "+f"(c[2]), "+f"(c[3])
        : "r"(a[0]), "r"(a[1]), "r"(a[2]), "r"(a[3]), "r"(b[0]), "r"(b[1]));
}

#define CP_ASYNC16(saddr, gptr) \
    asm volatile("cp.async.cg.shared.global [%0], [%1], 16;" :: "r"(saddr), "l"(gptr))
#define CP_COMMIT() asm volatile("cp.async.commit_group;")
#define CP_WAIT2()  asm volatile("cp.async.wait_group 2;")

__device__ __forceinline__ unsigned tf32_hi_bits(float x) {
    return __float_as_uint(x) & 0xFFFFE000u;
}

__global__ __launch_bounds__(256, 1) void sgemm_xg_tc(
    const float* __restrict__ A, const float* __restrict__ W,
    const float* __restrict__ bias, float* __restrict__ out, int K)
{
    extern __shared__ float sg[];

    const int tid  = threadIdx.x;
    const int cCol = blockIdx.x;   // 0..15  (n block)
    const int cRow = blockIdx.y;   // 0..511 (m block)

    const float* Ap = A + (size_t)cRow * 128 * K;
    const float* Wp = W + (size_t)cCol * 128;

    unsigned sbase;
    {
        unsigned long long t64;
        asm("cvta.to.shared.u64 %0, %1;" : "=l"(t64) : "l"(sg));
        sbase = (unsigned)t64;
    }

    const int nk = K >> 5;   // chunks of 32

    // copy-role indices (4 float4 each for A and B)
    const int amRow[4] = { (tid + 0) >> 3, (tid + 256) >> 3, (tid + 512) >> 3, (tid + 768) >> 3 };
    const int amQ     = (tid & 7) * 4;
    const int bkRow[4] = { (tid + 0) >> 5, (tid + 256) >> 5, (tid + 512) >> 5, (tid + 768) >> 5 };
    const int bQ      = (tid & 31) * 4;

    // warp roles
    const int wid  = tid >> 5;
    const int lane = tid & 31;
    const int wm   = (wid >> 2) * 64;   // 0 or 64
    const int wn   = (wid & 3) * 32;    // 0,32,64,96
    const int lg   = lane >> 2;         // 0..7
    const int lc   = lane & 3;          // 0..3

    float acc[4][4][4];
#pragma unroll
    for (int i = 0; i < 4; i++)
#pragma unroll
        for (int j = 0; j < 4; j++)
#pragma unroll
            for (int r = 0; r < 4; r++) acc[i][j][r] = 0.f;

    // issue one chunk's copies into a stage
    auto issue = [&](int ci, int st) {
        const int k0 = ci * 32;
        unsigned sa = sbase + (unsigned)(st * STAGE_FLOATS) * 4u;
        unsigned sb = sa + 128u * A_STRIDE * 4u;
#pragma unroll
        for (int j = 0; j < 4; j++) {
            const float* src = &Ap[(size_t)amRow[j] * K + k0 + amQ];
            CP_ASYNC16(sa + (unsigned)(amRow[j] * A_STRIDE + amQ) * 4u, src);
        }
#pragma unroll
        for (int j = 0; j < 4; j++) {
            const float* src = &Wp[(size_t)(k0 + bkRow[j]) * Gz + bQ];
            CP_ASYNC16(sb + (unsigned)(bkRow[j] * B_STRIDE + bQ) * 4u, src);
        }
        CP_COMMIT();
    };

    issue(0, 0);
    issue(nk > 1 ? 1 : 0, 1);
    issue(nk > 2 ? 2 : 0, 2);

    for (int ci = 0; ci < nk; ci++) {
        CP_WAIT2();              // oldest group (stage ci%3) complete
        __syncthreads();

        const int st = ci % 3;
        const float* As = sg + st * STAGE_FLOATS;
        const float* Bs = As + 128 * A_STRIDE;

#pragma unroll
        for (int k8 = 0; k8 < 4; k8++) {
            // A fragments (4 m16 tiles), hi/lo split
            unsigned ah[4][4], al[4][4];
#pragma unroll
            for (int i = 0; i < 4; i++) {
                int r0 = wm + 16 * i + lg;
                int c0 = k8 * 8 + lc;
                float a0 = As[r0 * A_STRIDE + c0];
                float a1 = As[(r0 + 8) * A_STRIDE + c0];
                float a2 = As[r0 * A_STRIDE + c0 + 4];
                float a3 = As[(r0 + 8) * A_STRIDE + c0 + 4];
                ah[i][0] = tf32_hi_bits(a0); al[i][0] = __float_as_uint(a0 - __uint_as_float(ah[i][0]));
                ah[i][1] = tf32_hi_bits(a1); al[i][1] = __float_as_uint(a1 - __uint_as_float(ah[i][1]));
                ah[i][2] = tf32_hi_bits(a2); al[i][2] = __float_as_uint(a2 - __uint_as_float(ah[i][2]));
                ah[i][3] = tf32_hi_bits(a3); al[i][3] = __float_as_uint(a3 - __uint_as_float(ah[i][3]));
            }
            // B fragments (4 n8 tiles), hi/lo split
            unsigned bh[4][2], bl[4][2];
#pragma unroll
            for (int j = 0; j < 4; j++) {
                int col = wn + 8 * j + lg;
                int row = k8 * 8 + lc;
                float b0 = Bs[row * B_STRIDE + col];
                float b1 = Bs[(row + 4) * B_STRIDE + col];
                bh[j][0] = tf32_hi_bits(b0); bl[j][0] = __float_as_uint(b0 - __uint_as_float(bh[j][0]));
                bh[j][1] = tf32_hi_bits(b1); bl[j][1] = __float_as_uint(b1 - __uint_as_float(bh[j][1]));
            }
#pragma unroll
            for (int i = 0; i < 4; i++)
#pragma unroll
                for (int j = 0; j < 4; j++) {
                    mma_tf32(acc[i][j], ah[i], bh[j]);
                    mma_tf32(acc[i][j], ah[i], bl[j]);
                    mma_tf32(acc[i][j], al[i], bh[j]);
                }
        }
        __syncthreads();
        issue(ci + 3 < nk ? ci + 3 : nk - 1, st);
    }

    // epilogue: scatter to out[t][b][n] with bias
    const int ncta = cCol * 128;
#pragma unroll
    for (int i = 0; i < 4; i++) {
        int m0 = cRow * 128 + wm + 16 * i + lg;
#pragma unroll
        for (int j = 0; j < 4; j++) {
            int n = ncta + wn + 8 * j + 2 * lc;
            float2 bv = *reinterpret_cast<const float2*>(&bias[n]);
            {
                int bb = m0 >> 10, tt = m0 & 1023;
                float* orow = &out[(size_t)((tt << 6) + bb) << 11];
                float2 r = { acc[i][j][0] + bv.x, acc[i][j][1] + bv.y };
                *reinterpret_cast<float2*>(&orow[n]) = r;
            }
            {
                int m1 = m0 + 8;
                int bb = m1 >> 10, tt = m1 & 1023;
                float* orow = &out[(size_t)((tt << 6) + bb) << 11];
                float2 r = { acc[i][j][2] + bv.x, acc[i][j][3] + bv.y };
                *reinterpret_cast<float2*>(&orow[n]) = r;
            }
        }
    }
}

// ---------------------------------------------------------------------------
// reset: zero h ping buffer 0 + barrier counter
// ---------------------------------------------------------------------------
__global__ void reset_state()
{
    int i = blockIdx.x * 512 + threadIdx.x;
    g_hping[0][i] = 0.f;
    if (i == 0) g_bar = 0u;
}

// ---------------------------------------------------------------------------
// Persistent LSTM recurrence (Round-1 version, known-good).
// ---------------------------------------------------------------------------
#define SH_STRIDE 68
#define REC_SMEM  ((512 * SH_STRIDE + 512 * 16 + 8 * 1024) * 4)   // 204800 B

__device__ __forceinline__ float sigmoidf_(float x) { return 1.f / (1.f + expf(-x)); }

__global__ __launch_bounds__(256) void lstm_rec(
    const float* __restrict__ Wh,    // [512][2048]
    const float* __restrict__ xgp,   // [T][B][2048]
    float* __restrict__ hout)        // [B][T][512]
{
    extern __shared__ float sm[];
    float* sH = sm;                       // [512][68]
    float* sW = sm + 512 * SH_STRIDE;     // [512][16]
    float* sR = sW + 512 * 16;            // [8][16][64]

    const int tid = threadIdx.x;
    const int u0  = blockIdx.x * 4;

    for (int i = tid; i < 512 * 16; i += 256) {
        int k = i >> 4, c = i & 15;
        int gate = c >> 2, un = c & 3;
        sW[i] = Wh[(size_t)k * Gz + gate * Hz + u0 + un];
    }

    const int ks = tid >> 5;
    const int rem = tid & 31;
    const int c2 = rem >> 4;
    const int b4 = rem & 15;
    const int sb = tid >> 2;
    const int sq = tid & 3;
    const int fb = tid & 63;
    const int fu = tid >> 6;

    float creg = 0.f;
    __syncthreads();

    for (int t = 0; t < Tz; t++) {
        const float* hp = &g_hping[t & 1][0];
#pragma unroll 8
        for (int i2 = 0; i2 < 32; i2++) {
            int k4 = i2 * 4 + sq;
            float4 v = __ldcg(reinterpret_cast<const float4*>(&hp[sb * 512 + (k4 << 2)]));
            int kb = k4 << 2;
            sH[(kb + 0) * SH_STRIDE + sb] = v.x;
            sH[(kb + 1) * SH_STRIDE + sb] = v.y;
            sH[(kb + 2) * SH_STRIDE + sb] = v.z;
            sH[(kb + 3) * SH_STRIDE + sb] = v.w;
        }
        __syncthreads();

        float acc[4][8];
#pragma unroll
        for (int i = 0; i < 4; i++)
#pragma unroll
            for (int j = 0; j < 8; j++) acc[i][j] = 0.f;

        const int kbase = ks * 64;
#pragma unroll 8
        for (int kk = 0; kk < 64; kk++) {
            int k = kbase + kk;
            float4 hv = *reinterpret_cast<const float4*>(&sH[k * SH_STRIDE + (b4 << 2)]);
            float4 w0 = *reinterpret_cast<const float4*>(&sW[(k << 4) + c2 * 8]);
            float4 w1 = *reinterpret_cast<const float4*>(&sW[(k << 4) + c2 * 8 + 4]);
            float hr[4] = {hv.x, hv.y, hv.z, hv.w};
            float wr[8] = {w0.x, w0.y, w0.z, w0.w, w1.x, w1.y, w1.z, w1.w};
#pragma unroll
            for (int i = 0; i < 4; i++)
#pragma unroll
                for (int j = 0; j < 8; j++) acc[i][j] += hr[i] * wr[j];
        }

#pragma unroll
        for (int i = 0; i < 4; i++)
#pragma unroll
            for (int j = 0; j < 8; j++)
                sR[(ks << 10) + ((c2 * 8 + j) << 6) + (b4 << 2) + i] = acc[i][j];
        __syncthreads();

        float gv[4];
#pragma unroll
        for (int g = 0; g < 4; g++) {
            int c = (g << 2) + fu;
            float s = 0.f;
#pragma unroll
            for (int kq = 0; kq < 8; kq++) s += sR[(kq << 10) + (c << 6) + fb];
            gv[g] = s + xgp[(size_t)((t << 6) + fb) * Gz + (g << 9) + u0 + fu];
        }
        float ig = sigmoidf_(gv[0]);
        float fg = sigmoidf_(gv[1]);
        float gg = tanhf(gv[2]);
        float og = sigmoidf_(gv[3]);
        creg = fg * creg + ig * gg;
        float hv = og * tanhf(creg);

        g_hping[(t & 1) ^ 1][fb * 512 + u0 + fu] = hv;
        hout[(size_t)((fb << 10) + t) * Hz + u0 + fu] = hv;

        __threadfence();
        __syncthreads();
        if (tid == 0) {
            atomicAdd(&g_bar, 1u);
            unsigned tgt = (unsigned)(t + 1) * gridDim.x;
            volatile unsigned* vb = &g_bar;
            while (*vb < tgt) {}
        }
        __syncthreads();
    }
}

// ---------------------------------------------------------------------------
// BatchNorm (deterministic two-stage) + apply + head
// ---------------------------------------------------------------------------
__global__ void bn_partial(const float* __restrict__ h)
{
    int f = blockIdx.x * 128 + threadIdx.x;    // grid.x = 4
    int chunk = blockIdx.y;                    // grid.y = NCHUNK
    const float* p = h + (size_t)chunk * (BT / NCHUNK) * Hz + f;
    float s = 0.f, s2 = 0.f;
    for (int r = 0; r < BT / NCHUNK; r++) {
        float v = p[(size_t)r * Hz];
        s += v; s2 += v * v;
    }
    g_ps [chunk * Hz + f] = s;
    g_ps2[chunk * Hz + f] = s2;
}

__global__ void bn_finalize(const float* __restrict__ scale, const float* __restrict__ bias)
{
    int f = blockIdx.x * 128 + threadIdx.x;
    float s = 0.f, s2 = 0.f;
    for (int c = 0; c < NCHUNK; c++) { s += g_ps[c * Hz + f]; s2 += g_ps2[c * Hz + f]; }
    float mean = s * (1.f / 65536.f);
    float var  = s2 * (1.f / 65536.f) - mean * mean;
    float rstd = rsqrtf(var + 1e-5f);
    float a = rstd * scale[f];
    g_bnA[f] = a;
    g_bnB[f] = bias[f] - mean * a;
}

__global__ void bn_apply(float* __restrict__ h)
{
    int idx = blockIdx.x * 256 + threadIdx.x;
    float4 v = reinterpret_cast<float4*>(h)[idx];
    int f = (idx & 127) * 4;
    float4 a = *reinterpret_cast<const float4*>(&g_bnA[f]);
    float4 b = *reinterpret_cast<const float4*>(&g_bnB[f]);
    v.x = v.x * a.x + b.x;
    v.y = v.y * a.y + b.y;
    v.z = v.z * a.z + b.z;
    v.w = v.w * a.w + b.w;
    reinterpret_cast<float4*>(h)[idx] = v;
}

__global__ void head_kernel(const float* __restrict__ h2,
                            const float* __restrict__ Wd1, const float* __restrict__ bd1,
                            const float* __restrict__ Wd2, const float* __restrict__ bd2,
                            float* __restrict__ out)
{
    __shared__ float sh[512];
    __shared__ float sy[16];
    int b = blockIdx.x;
    int tid = threadIdx.x;
    float v = h2[((size_t)b * 1024 + 1023) * Hz + tid];
    sh[tid] = v * g_bnA[tid] + g_bnB[tid];
    __syncthreads();

    int w = tid >> 5, lane = tid & 31;
    float s = 0.f;
    for (int f = lane; f < 512; f += 32) s += sh[f] * Wd1[f * 16 + w];
#pragma unroll
    for (int off = 16; off; off >>= 1) s += __shfl_down_sync(0xffffffffu, s, off);
    if (lane == 0) sy[w] = fmaxf(s + bd1[w], 0.f);
    __syncthreads();
    if (tid == 0) {
        float o = bd2[0];
#pragma unroll
        for (int j = 0; j < 16; j++) o += sy[j] * Wd2[j];
        out[b] = o;
    }
}

// ---------------------------------------------------------------------------
extern "C" void kernel_launch(void* const* d_in, const int* in_sizes, int n_in,
                              void* d_out, int out_size)
{
    const float* x    = (const float*)d_in[0];
    const float* Wx1  = (const float*)d_in[1];
    const float* Wh1  = (const float*)d_in[2];
    const float* b1   = (const float*)d_in[3];
    const float* s1   = (const float*)d_in[4];
    const float* bi1  = (const float*)d_in[5];
    const float* Wx2  = (const float*)d_in[6];
    const float* Wh2  = (const float*)d_in[7];
    const float* b2   = (const float*)d_in[8];
    const float* s2   = (const float*)d_in[9];
    const float* bi2  = (const float*)d_in[10];
    const float* Wd1  = (const float*)d_in[11];
    const float* bd1  = (const float*)d_in[12];
    const float* Wd2  = (const float*)d_in[13];
    const float* bd2  = (const float*)d_in[14];
    float* out = (float*)d_out;

    float *xg, *h1, *h2;
    cudaGetSymbolAddress((void**)&xg, g_xg);
    cudaGetSymbolAddress((void**)&h1, g_h1);
    cudaGetSymbolAddress((void**)&h2, g_h2);

    cudaFuncSetAttribute(lstm_rec, cudaFuncAttributeMaxDynamicSharedMemorySize, REC_SMEM);
    cudaFuncSetAttribute(sgemm_xg_tc, cudaFuncAttributeMaxDynamicSharedMemorySize, GEMM_SMEM);

    // layer 1
    sgemm_xg_tc<<<dim3(16, 512), 256, GEMM_SMEM>>>(x, Wx1, b1, xg, Dz);
    reset_state<<<64, 512>>>();
    lstm_rec<<<128, 256, REC_SMEM>>>(Wh1, xg, h1);
    bn_partial<<<dim3(4, NCHUNK), 128>>>(h1);
    bn_finalize<<<4, 128>>>(s1, bi1);
    bn_apply<<<32768, 256>>>(h1);

    // layer 2
    sgemm_xg_tc<<<dim3(16, 512), 256, GEMM_SMEM>>>(h1, Wx2, b2, xg, Hz);
    reset_state<<<64, 512>>>();
    lstm_rec<<<128, 256, REC_SMEM>>>(Wh2, xg, h2);
    bn_partial<<<dim3(4, NCHUNK), 128>>>(h2);
    bn_finalize<<<4, 128>>>(s2, bi2);

    // head (applies bn2 to last timestep only)
    head_kernel<<<64, 512>>>(h2, Wd1, bd1, Wd2, bd2, out);
}

// round 4
// speedup vs baseline: 1.3480x; 1.1760x over previous
#include <cuda_runtime.h>
#include <math.h>

typedef unsigned long long ull;

// Problem constants
#define Bz   64
#define Tz   1024
#define Dz   128
#define Hz   512
#define Gz   2048          // 4*H
#define BT   65536         // B*T
#define NCHUNK 256         // bn partial chunks

// ---------------- scratch (device globals; no cudaMalloc allowed) ----------
__device__ float    g_xg[(size_t)Tz * Bz * Gz];     // [T][B][4H]
__device__ float    g_h1[(size_t)BT * Hz];          // [B][T][H]
__device__ float    g_h2[(size_t)BT * Hz];          // [B][T][H]
__device__ float    g_hping[2][Bz * Hz];            // recurrent h double buffer
__device__ unsigned g_bar;                          // grid barrier counter
__device__ float    g_ps [NCHUNK * Hz];             // BN partial sums
__device__ float    g_ps2[NCHUNK * Hz];
__device__ float    g_bnA[Hz];                      // folded BN scale
__device__ float    g_bnB[Hz];                      // folded BN bias

// ---------------- f32x2 helpers --------------------------------------------
__device__ __forceinline__ ull pack2(float x, float y) {
    ull r;
    asm("mov.b64 %0, {%1, %2};" : "=l"(r) : "f"(x), "f"(y));
    return r;
}
__device__ __forceinline__ float unpack_sum(ull v) {
    float lo, hi;
    asm("mov.b64 {%0, %1}, %2;" : "=f"(lo), "=f"(hi) : "l"(v));
    return lo + hi;
}
#define FMA2(acc, a, b) asm("fma.rn.f32x2 %0, %1, %2, %0;" : "+l"(acc) : "l"(a), "l"(b))

#define CP_ASYNC16(saddr, gptr) \
    asm volatile("cp.async.cg.shared.global [%0], [%1], 16;" :: "r"(saddr), "l"(gptr))
#define CP_COMMIT() asm volatile("cp.async.commit_group;")
#define CP_WAIT0()  asm volatile("cp.async.wait_group 0;")
#define CP_WAIT2()  asm volatile("cp.async.wait_group 2;")

// ---------------------------------------------------------------------------
// Tensor-core SGEMM (tf32 x3 precision split) — unchanged from R3 (proven).
// ---------------------------------------------------------------------------
#define A_STRIDE 36
#define B_STRIDE 136
#define STAGE_FLOATS (128 * A_STRIDE + 32 * B_STRIDE)
#define GEMM_SMEM (3 * STAGE_FLOATS * 4)

__device__ __forceinline__ void mma_tf32(float* c, const unsigned* a, const unsigned* b)
{
    asm volatile(
        "mma.sync.aligned.m16n8k8.row.col.f32.tf32.tf32.f32 "
        "{%0,%1,%2,%3}, {%4,%5,%6,%7}, {%8,%9}, {%0,%1,%2,%3};"
        : "+f"(c[0]), "+f"(c[1]), "+f"(c[2]), "+f"(c[3])
        : "r"(a[0]), "r"(a[1]), "r"(a[2]), "r"(a[3]), "r"(b[0]), "r"(b[1]));
}

__device__ __forceinline__ unsigned tf32_hi_bits(float x) {
    return __float_as_uint(x) & 0xFFFFE000u;
}

__global__ __launch_bounds__(256, 1) void sgemm_xg_tc(
    const float* __restrict__ A, const float* __restrict__ W,
    const float* __restrict__ bias, float* __restrict__ out, int K)
{
    extern __shared__ float sg[];

    const int tid  = threadIdx.x;
    const int cCol = blockIdx.x;
    const int cRow = blockIdx.y;

    const float* Ap = A + (size_t)cRow * 128 * K;
    const float* Wp = W + (size_t)cCol * 128;

    unsigned sbase;
    {
        unsigned long long t64;
        asm("cvta.to.shared.u64 %0, %1;" : "=l"(t64) : "l"(sg));
        sbase = (unsigned)t64;
    }

    const int nk = K >> 5;

    const int amRow[4] = { (tid + 0) >> 3, (tid + 256) >> 3, (tid + 512) >> 3, (tid + 768) >> 3 };
    const int amQ     = (tid & 7) * 4;
    const int bkRow[4] = { (tid + 0) >> 5, (tid + 256) >> 5, (tid + 512) >> 5, (tid + 768) >> 5 };
    const int bQ      = (tid & 31) * 4;

    const int wid  = tid >> 5;
    const int lane = tid & 31;
    const int wm   = (wid >> 2) * 64;
    const int wn   = (wid & 3) * 32;
    const int lg   = lane >> 2;
    const int lc   = lane & 3;

    float acc[4][4][4];
#pragma unroll
    for (int i = 0; i < 4; i++)
#pragma unroll
        for (int j = 0; j < 4; j++)
#pragma unroll
            for (int r = 0; r < 4; r++) acc[i][j][r] = 0.f;

    auto issue = [&](int ci, int st) {
        const int k0 = ci * 32;
        unsigned sa = sbase + (unsigned)(st * STAGE_FLOATS) * 4u;
        unsigned sb = sa + 128u * A_STRIDE * 4u;
#pragma unroll
        for (int j = 0; j < 4; j++) {
            const float* src = &Ap[(size_t)amRow[j] * K + k0 + amQ];
            CP_ASYNC16(sa + (unsigned)(amRow[j] * A_STRIDE + amQ) * 4u, src);
        }
#pragma unroll
        for (int j = 0; j < 4; j++) {
            const float* src = &Wp[(size_t)(k0 + bkRow[j]) * Gz + bQ];
            CP_ASYNC16(sb + (unsigned)(bkRow[j] * B_STRIDE + bQ) * 4u, src);
        }
        CP_COMMIT();
    };

    issue(0, 0);
    issue(nk > 1 ? 1 : 0, 1);
    issue(nk > 2 ? 2 : 0, 2);

    for (int ci = 0; ci < nk; ci++) {
        CP_WAIT2();
        __syncthreads();

        const int st = ci % 3;
        const float* As = sg + st * STAGE_FLOATS;
        const float* Bs = As + 128 * A_STRIDE;

#pragma unroll
        for (int k8 = 0; k8 < 4; k8++) {
            unsigned ah[4][4], al[4][4];
#pragma unroll
            for (int i = 0; i < 4; i++) {
                int r0 = wm + 16 * i + lg;
                int c0 = k8 * 8 + lc;
                float a0 = As[r0 * A_STRIDE + c0];
                float a1 = As[(r0 + 8) * A_STRIDE + c0];
                float a2 = As[r0 * A_STRIDE + c0 + 4];
                float a3 = As[(r0 + 8) * A_STRIDE + c0 + 4];
                ah[i][0] = tf32_hi_bits(a0); al[i][0] = __float_as_uint(a0 - __uint_as_float(ah[i][0]));
                ah[i][1] = tf32_hi_bits(a1); al[i][1] = __float_as_uint(a1 - __uint_as_float(ah[i][1]));
                ah[i][2] = tf32_hi_bits(a2); al[i][2] = __float_as_uint(a2 - __uint_as_float(ah[i][2]));
                ah[i][3] = tf32_hi_bits(a3); al[i][3] = __float_as_uint(a3 - __uint_as_float(ah[i][3]));
            }
            unsigned bh[4][2], bl[4][2];
#pragma unroll
            for (int j = 0; j < 4; j++) {
                int col = wn + 8 * j + lg;
                int row = k8 * 8 + lc;
                float b0 = Bs[row * B_STRIDE + col];
                float b1 = Bs[(row + 4) * B_STRIDE + col];
                bh[j][0] = tf32_hi_bits(b0); bl[j][0] = __float_as_uint(b0 - __uint_as_float(bh[j][0]));
                bh[j][1] = tf32_hi_bits(b1); bl[j][1] = __float_as_uint(b1 - __uint_as_float(bh[j][1]));
            }
#pragma unroll
            for (int i = 0; i < 4; i++)
#pragma unroll
                for (int j = 0; j < 4; j++) {
                    mma_tf32(acc[i][j], ah[i], bh[j]);
                    mma_tf32(acc[i][j], ah[i], bl[j]);
                    mma_tf32(acc[i][j], al[i], bh[j]);
                }
        }
        __syncthreads();
        issue(ci + 3 < nk ? ci + 3 : nk - 1, st);
    }

    const int ncta = cCol * 128;
#pragma unroll
    for (int i = 0; i < 4; i++) {
        int m0 = cRow * 128 + wm + 16 * i + lg;
#pragma unroll
        for (int j = 0; j < 4; j++) {
            int n = ncta + wn + 8 * j + 2 * lc;
            float2 bv = *reinterpret_cast<const float2*>(&bias[n]);
            {
                int bb = m0 >> 10, tt = m0 & 1023;
                float* orow = &out[(size_t)((tt << 6) + bb) << 11];
                float2 r = { acc[i][j][0] + bv.x, acc[i][j][1] + bv.y };
                *reinterpret_cast<float2*>(&orow[n]) = r;
            }
            {
                int m1 = m0 + 8;
                int bb = m1 >> 10, tt = m1 & 1023;
                float* orow = &out[(size_t)((tt << 6) + bb) << 11];
                float2 r = { acc[i][j][2] + bv.x, acc[i][j][3] + bv.y };
                *reinterpret_cast<float2*>(&orow[n]) = r;
            }
        }
    }
}

// ---------------------------------------------------------------------------
__global__ void reset_state()
{
    int i = blockIdx.x * 512 + threadIdx.x;
    g_hping[0][i] = 0.f;
    if (i == 0) g_bar = 0u;
}

// ---------------------------------------------------------------------------
// Persistent LSTM recurrence v2.
// 128 CTAs = 4 batch-quarters x 32 unit-groups. CTA: 16 batches x 16 units
// (64 gate cols). f32x2 k-packed dot, thread tile 4b x 8c (acc = 32 ull = 64 regs).
// smem: sW2 ull[256 k2][80 slots]  (c-group g at slot g*10; conflict-free) 160KB
//       sH2 ull[256 k2][16 b]      32KB   (aliased by sR float[8][16][64] post-dot)
//       sXG float[16][64]          4KB    (cp.async prefetched xg gate tile)
// ---------------------------------------------------------------------------
#define SW2_ROW 80
#define REC_SMEM ((256 * SW2_ROW + 256 * 16) * 8 + 16 * 64 * 4)   // 163840+32768+4096 = 200704

__device__ __forceinline__ float sigmoidf_(float x) { return 1.f / (1.f + expf(-x)); }

__global__ __launch_bounds__(256) void lstm_rec(
    const float* __restrict__ Wh,    // [512][2048]
    const float* __restrict__ xgp,   // [T][B][2048]
    float* __restrict__ hout)        // [B][T][512]
{
    extern __shared__ ull smu[];
    ull*   sW2 = smu;                          // 256*80 ull
    ull*   sH2 = smu + 256 * SW2_ROW;          // 256*16 ull
    float* sR  = reinterpret_cast<float*>(sH2);           // alias (32KB), guarded
    float* sXG = reinterpret_cast<float*>(sH2 + 256 * 16); // 1024 floats

    const int tid = threadIdx.x;
    const int ug  = blockIdx.x & 31;         // unit group
    const int bq  = blockIdx.x >> 5;         // batch quarter
    const int u0  = ug * 16;
    const int b0  = bq * 16;

    unsigned sxg_base;
    {
        unsigned long long t64;
        asm("cvta.to.shared.u64 %0, %1;" : "=l"(t64) : "l"(sXG));
        sxg_base = (unsigned)t64;
    }

    // ---- load Wh slice: sW2[k2][slot(c)] = pack(Wh[2k2][col], Wh[2k2+1][col])
    // c = gate*16 + unit(0..15); slot(c) = (c>>3)*10 + (c&7)
    for (int i = tid; i < 256 * 64; i += 256) {
        int k2 = i >> 6, c = i & 63;
        int gate = c >> 4, un = c & 15;
        int col = gate * Hz + u0 + un;
        float lo = Wh[(size_t)(2 * k2 + 0) * Gz + col];
        float hi = Wh[(size_t)(2 * k2 + 1) * Gz + col];
        sW2[k2 * SW2_ROW + (c >> 3) * 10 + (c & 7)] = pack2(lo, hi);
    }

    // dot roles: 8 warps = 8 k-splits; lane = bg*8 + cg (4 b-groups x 8 c-groups)
    const int ks = tid >> 5;
    const int lane = tid & 31;
    const int bg = lane >> 3;              // 0..3  -> batches bg*4..+3
    const int cg = lane & 7;               // 0..7  -> cols cg*8..+7
    // stage roles: 256 threads load 16 rows x 512 floats (8 float4 each)
    const int sb = tid >> 4;               // 0..15 local batch
    const int sq = tid & 15;               // float4 column index base
    // finalize roles
    const int fu  = tid & 15;              // unit
    const int fbL = tid >> 4;              // local batch
    // xg prefetch roles: tid -> (row = tid>>4, seg = tid&15)
    const int xrow = tid >> 4;
    const int xseg = tid & 15;
    const int xgate = xseg >> 2;
    const int xun   = (xseg & 3) * 4;

    float creg = 0.f;
    __syncthreads();

    for (int t = 0; t < Tz; t++) {
        // ---- prefetch xg tile for this step (needed only at finalize) ----
        {
            const float* src = &xgp[(size_t)((t << 6) + b0 + xrow) * Gz + (xgate << 9) + u0 + xun];
            CP_ASYNC16(sxg_base + (unsigned)(xrow * 64 + xseg * 4) * 4u, src);
            CP_COMMIT();
        }

        // ---- stage h_prev rows b0..b0+15 -> sH2[k2][bL] as k-pairs ----
        const float* hp = &g_hping[t & 1][0];
#pragma unroll 4
        for (int i2 = 0; i2 < 8; i2++) {
            int k4 = i2 * 16 + sq;                  // float4 index 0..127
            float4 v = __ldcg(reinterpret_cast<const float4*>(&hp[(b0 + sb) * 512 + (k4 << 2)]));
            int k2a = k4 << 1;
            sH2[(k2a + 0) * 16 + sb] = pack2(v.x, v.y);
            sH2[(k2a + 1) * 16 + sb] = pack2(v.z, v.w);
        }
        __syncthreads();

        // ---- dot: this warp's 32 k2 rows; acc[4b][8c] packed over k ----
        ull acc[4][8];
#pragma unroll
        for (int i = 0; i < 4; i++)
#pragma unroll
            for (int j = 0; j < 8; j++) acc[i][j] = 0ull;

        const int k2base = ks * 32;
#pragma unroll 4
        for (int kk = 0; kk < 32; kk++) {
            int k2 = k2base + kk;
            ull hr[4], wr[8];
            const ulonglong2* hp2 = reinterpret_cast<const ulonglong2*>(&sH2[k2 * 16 + bg * 4]);
            { ulonglong2 v0 = hp2[0], v1 = hp2[1];
              hr[0] = v0.x; hr[1] = v0.y; hr[2] = v1.x; hr[3] = v1.y; }
            const ulonglong2* wp2 = reinterpret_cast<const ulonglong2*>(&sW2[k2 * SW2_ROW + cg * 10]);
#pragma unroll
            for (int q = 0; q < 4; q++) { ulonglong2 v = wp2[q]; wr[2 * q] = v.x; wr[2 * q + 1] = v.y; }
#pragma unroll
            for (int i = 0; i < 4; i++)
#pragma unroll
                for (int j = 0; j < 8; j++) FMA2(acc[i][j], hr[i], wr[j]);
        }
        __syncthreads();   // sH2 reads complete before sR (alias) writes

        // ---- write split partials: sR[ks][bL][c] (c = cg*8+j) ----
#pragma unroll
        for (int i = 0; i < 4; i++) {
            float4 r0, r1;
            r0.x = unpack_sum(acc[i][0]); r0.y = unpack_sum(acc[i][1]);
            r0.z = unpack_sum(acc[i][2]); r0.w = unpack_sum(acc[i][3]);
            r1.x = unpack_sum(acc[i][4]); r1.y = unpack_sum(acc[i][5]);
            r1.z = unpack_sum(acc[i][6]); r1.w = unpack_sum(acc[i][7]);
            float* dst = &sR[(ks << 10) + ((bg * 4 + i) << 6) + (cg << 3)];
            *reinterpret_cast<float4*>(dst)     = r0;
            *reinterpret_cast<float4*>(dst + 4) = r1;
        }
        CP_WAIT0();
        __syncthreads();

        // ---- finalize: reduce 8 splits + xg, gate math, write h ----
        float gv[4];
#pragma unroll
        for (int g = 0; g < 4; g++) {
            int c = (g << 4) + fu;
            float s = 0.f;
#pragma unroll
            for (int kq = 0; kq < 8; kq++) s += sR[(kq << 10) + (fbL << 6) + c];
            gv[g] = s + sXG[(fbL << 6) + c];
        }
        float ig = sigmoidf_(gv[0]);
        float fg = sigmoidf_(gv[1]);
        float gg = tanhf(gv[2]);
        float og = sigmoidf_(gv[3]);
        creg = fg * creg + ig * gg;
        float hv = og * tanhf(creg);

        int gb = b0 + fbL;
        g_hping[(t & 1) ^ 1][gb * 512 + u0 + fu] = hv;
        hout[(size_t)((gb << 10) + t) * Hz + u0 + fu] = hv;

        // ---- grid barrier ----
        __threadfence();
        __syncthreads();
        if (tid == 0) {
            atomicAdd(&g_bar, 1u);
            unsigned tgt = (unsigned)(t + 1) * gridDim.x;
            volatile unsigned* vb = &g_bar;
            while (*vb < tgt) {}
        }
        __syncthreads();
    }
}

// ---------------------------------------------------------------------------
// BatchNorm (deterministic two-stage) + apply + head
// ---------------------------------------------------------------------------
__global__ void bn_partial(const float* __restrict__ h)
{
    int f = blockIdx.x * 128 + threadIdx.x;
    int chunk = blockIdx.y;
    const float* p = h + (size_t)chunk * (BT / NCHUNK) * Hz + f;
    float s = 0.f, s2 = 0.f;
    for (int r = 0; r < BT / NCHUNK; r++) {
        float v = p[(size_t)r * Hz];
        s += v; s2 += v * v;
    }
    g_ps [chunk * Hz + f] = s;
    g_ps2[chunk * Hz + f] = s2;
}

__global__ void bn_finalize(const float* __restrict__ scale, const float* __restrict__ bias)
{
    int f = blockIdx.x * 128 + threadIdx.x;
    float s = 0.f, s2 = 0.f;
    for (int c = 0; c < NCHUNK; c++) { s += g_ps[c * Hz + f]; s2 += g_ps2[c * Hz + f]; }
    float mean = s * (1.f / 65536.f);
    float var  = s2 * (1.f / 65536.f) - mean * mean;
    float rstd = rsqrtf(var + 1e-5f);
    float a = rstd * scale[f];
    g_bnA[f] = a;
    g_bnB[f] = bias[f] - mean * a;
}

__global__ void bn_apply(float* __restrict__ h)
{
    int idx = blockIdx.x * 256 + threadIdx.x;
    float4 v = reinterpret_cast<float4*>(h)[idx];
    int f = (idx & 127) * 4;
    float4 a = *reinterpret_cast<const float4*>(&g_bnA[f]);
    float4 b = *reinterpret_cast<const float4*>(&g_bnB[f]);
    v.x = v.x * a.x + b.x;
    v.y = v.y * a.y + b.y;
    v.z = v.z * a.z + b.z;
    v.w = v.w * a.w + b.w;
    reinterpret_cast<float4*>(h)[idx] = v;
}

__global__ void head_kernel(const float* __restrict__ h2,
                            const float* __restrict__ Wd1, const float* __restrict__ bd1,
                            const float* __restrict__ Wd2, const float* __restrict__ bd2,
                            float* __restrict__ out)
{
    __shared__ float sh[512];
    __shared__ float sy[16];
    int b = blockIdx.x;
    int tid = threadIdx.x;
    float v = h2[((size_t)b * 1024 + 1023) * Hz + tid];
    sh[tid] = v * g_bnA[tid] + g_bnB[tid];
    __syncthreads();

    int w = tid >> 5, lane = tid & 31;
    float s = 0.f;
    for (int f = lane; f < 512; f += 32) s += sh[f] * Wd1[f * 16 + w];
#pragma unroll
    for (int off = 16; off; off >>= 1) s += __shfl_down_sync(0xffffffffu, s, off);
    if (lane == 0) sy[w] = fmaxf(s + bd1[w], 0.f);
    __syncthreads();
    if (tid == 0) {
        float o = bd2[0];
#pragma unroll
        for (int j = 0; j < 16; j++) o += sy[j] * Wd2[j];
        out[b] = o;
    }
}

// ---------------------------------------------------------------------------
extern "C" void kernel_launch(void* const* d_in, const int* in_sizes, int n_in,
                              void* d_out, int out_size)
{
    const float* x    = (const float*)d_in[0];
    const float* Wx1  = (const float*)d_in[1];
    const float* Wh1  = (const float*)d_in[2];
    const float* b1   = (const float*)d_in[3];
    const float* s1   = (const float*)d_in[4];
    const float* bi1  = (const float*)d_in[5];
    const float* Wx2  = (const float*)d_in[6];
    const float* Wh2  = (const float*)d_in[7];
    const float* b2   = (const float*)d_in[8];
    const float* s2   = (const float*)d_in[9];
    const float* bi2  = (const float*)d_in[10];
    const float* Wd1  = (const float*)d_in[11];
    const float* bd1  = (const float*)d_in[12];
    const float* Wd2  = (const float*)d_in[13];
    const float* bd2  = (const float*)d_in[14];
    float* out = (float*)d_out;

    float *xg, *h1, *h2;
    cudaGetSymbolAddress((void**)&xg, g_xg);
    cudaGetSymbolAddress((void**)&h1, g_h1);
    cudaGetSymbolAddress((void**)&h2, g_h2);

    cudaFuncSetAttribute(lstm_rec, cudaFuncAttributeMaxDynamicSharedMemorySize, REC_SMEM);
    cudaFuncSetAttribute(sgemm_xg_tc, cudaFuncAttributeMaxDynamicSharedMemorySize, GEMM_SMEM);

    // layer 1
    sgemm_xg_tc<<<dim3(16, 512), 256, GEMM_SMEM>>>(x, Wx1, b1, xg, Dz);
    reset_state<<<64, 512>>>();
    lstm_rec<<<128, 256, REC_SMEM>>>(Wh1, xg, h1);
    bn_partial<<<dim3(4, NCHUNK), 128>>>(h1);
    bn_finalize<<<4, 128>>>(s1, bi1);
    bn_apply<<<32768, 256>>>(h1);

    // layer 2
    sgemm_xg_tc<<<dim3(16, 512), 256, GEMM_SMEM>>>(h1, Wx2, b2, xg, Hz);
    reset_state<<<64, 512>>>();
    lstm_rec<<<128, 256, REC_SMEM>>>(Wh2, xg, h2);
    bn_partial<<<dim3(4, NCHUNK), 128>>>(h2);
    bn_finalize<<<4, 128>>>(s2, bi2);

    // head (applies bn2 to last timestep only)
    head_kernel<<<64, 512>>>(h2, Wd1, bd1, Wd2, bd2, out);
}